// round 14
// baseline (speedup 1.0000x reference)
#include <cuda_runtime.h>
#include <cstdint>

#define SL   3264            // seq length L
#define KK   12
#define LPK  (SL / KK)       // 272
#define SS   8               // streams
#define BB   64              // batch
#define AA   4               // antennas
#define RR   (SL / 4)        // 816 (L / LOCC)
#define NOFF 21              // delay candidates -10..10
#define TILE 128             // l-tile for k_final
#define NTILE 26             // ceil(3264/128)
#define PDIM 816             // decimated length L/4

#define SMEM_DYN (AA * 2 * SL * 4)   // 104448 B

// ---- scratch (device-global: allocation-free contract) ----
__device__ int    g_m[SS * BB];                   // (t_off + ideal_peak) mod L
__device__ int    g_tt[SS * BB];                  // t_off mod L
__device__ float4 g_trig[SS * BB];                // (ms.x, ms.y, ts.x, ts.y)
__device__ float2 g_havg[SS * BB * AA * RR];      // OCC-averaged channel, 13.4 MB

// ---- packed f32x2 helpers (sm_103a dual-lane fp32) ----
#define F2MUL(o, a, b)    asm("mul.rn.f32x2 %0, %1, %2;"      : "=l"(o) : "l"(a), "l"(b))
#define F2FMA(o, a, b, c) asm("fma.rn.f32x2 %0, %1, %2, %3;"  : "=l"(o) : "l"(a), "l"(b), "l"(c))
#define F2ADD(o, a, b)    asm("add.rn.f32x2 %0, %1, %2;"      : "=l"(o) : "l"(a), "l"(b))
#define SGNMASK 0x8000000080000000ULL

static __device__ __forceinline__ uint64_t pk2(float lo, float hi) {
    uint64_t r; asm("mov.b64 %0, {%1, %2};" : "=l"(r) : "f"(lo), "f"(hi)); return r;
}
static __device__ __forceinline__ float lo2(uint64_t v) {
    float a, b; asm("mov.b64 {%0, %1}, %2;" : "=f"(a), "=f"(b) : "l"(v)); return a;
}
static __device__ __forceinline__ float hi2(uint64_t v) {
    float a, b; asm("mov.b64 {%0, %1}, %2;" : "=f"(a), "=f"(b) : "l"(v)); return b;
}
static __device__ __forceinline__ uint64_t splat(float v) { return pk2(v, v); }

// fp32 2*pi/L, matching reference fp32 angle math
#define WF ((float)(6.283185307179586476925286766559 / 3264.0))

// fast phasor: e^{i th k}; reduce to (-pi, pi] for MUFU accuracy
static __device__ __forceinline__ float2 phasor(int k) {
    if (k > SL / 2) k -= SL;
    float s, c;
    __sincosf(WF * (float)k, &s, &c);
    return make_float2(c, s);
}

static __device__ __forceinline__ int modL(int x) { x %= SL; return x < 0 ? x + SL : x; }

// packed complex in-place multiply: (ar,ai) *= (br,bi)
#define CMUL(ar, ai, br, bi) do {            \
    uint64_t _m, _nr;                        \
    F2MUL(_m, ai, bi); _m ^= SGNMASK;        \
    F2FMA(_nr, ar, br, _m);                  \
    F2MUL(_m, ai, br);                       \
    F2FMA(ai, ar, bi, _m);                   \
    ar = _nr;                                \
} while (0)

// ---- mbarrier / TMA-bulk helpers ----
static __device__ __forceinline__ uint32_t smem_u32(const void* p) {
    uint32_t r;
    asm("{ .reg .u64 t; cvta.to.shared.u64 t, %1; cvt.u32.u64 %0, t; }" : "=r"(r) : "l"(p));
    return r;
}
#define MBAR_INIT(addr, cnt) \
    asm volatile("mbarrier.init.shared.b64 [%0], %1;" :: "r"(addr), "r"(cnt) : "memory")
#define MBAR_EXPECT_TX(addr, bytes) \
    asm volatile("mbarrier.arrive.expect_tx.shared.b64 _, [%0], %1;" :: "r"(addr), "r"(bytes) : "memory")
#define TMA_BULK_G2S(dst, src, bytes, mbar) \
    asm volatile("cp.async.bulk.shared::cta.global.mbarrier::complete_tx::bytes [%0], [%1], %2, [%3];" \
        :: "r"(dst), "l"(src), "r"(bytes), "r"(mbar) : "memory")
static __device__ __forceinline__ void mbar_wait0(uint32_t addr) {
    asm volatile(
        "{\n\t"
        ".reg .pred P;\n\t"
        "WAIT_%=:\n\t"
        "mbarrier.try_wait.parity.acquire.cta.shared::cta.b64 P, [%0], 0, 0x989680;\n\t"
        "@P bra.uni DONE_%=;\n\t"
        "bra.uni WAIT_%=;\n\t"
        "DONE_%=:\n\t"
        "}" :: "r"(addr) : "memory");
}

// ---------------------------------------------------------------------------
// Chebyshev accumulation chunk for one class (unchanged, proven).
// ---------------------------------------------------------------------------
template <int S>
static __device__ __forceinline__ void eval_cheb(
    uint64_t Wr, uint64_t Wi, uint64_t sr, uint64_t si,
    uint64_t phir, uint64_t phii, uint64_t tc, uint64_t ntc,
    uint64_t* accr, uint64_t* acci)
{
    uint64_t m, v0r, v0i;
    F2MUL(m, Wi, si); m ^= SGNMASK;
    F2FMA(v0r, Wr, sr, m);
    F2MUL(m, Wi, sr);
    F2FMA(v0i, Wr, si, m);
    F2ADD(accr[0], accr[0], v0r);
    F2ADD(acci[0], acci[0], v0i);

    uint64_t v1r, v1i;
    F2MUL(m, v0i, phii); m ^= SGNMASK;
    F2FMA(v1r, v0r, phir, m);
    F2MUL(m, v0i, phir);
    F2FMA(v1i, v0r, phii, m);
    F2ADD(accr[1], accr[1], v1r);
    F2ADD(acci[1], acci[1], v1i);

    uint64_t pr = v0r, pi_ = v0i, cr = v1r, ci_ = v1i;
#pragma unroll
    for (int j = 2; j < S; j++) {
        uint64_t co = (j & 1) ? tc : ntc;
        uint64_t nr, ni;
        F2FMA(nr, co, cr, pr);
        F2FMA(ni, co, ci_, pi_);
        pr = cr; pi_ = ci_; cr = nr; ci_ = ni;
        F2ADD(accr[j], accr[j], nr);
        F2ADD(acci[j], acci[j], ni);
    }
}

// warp-reduce packed complex, lane0 writes |X|^2
template <int S>
static __device__ __forceinline__ void reduce_pows(
    float* powdst /*stride-4*/, const uint64_t* accr, const uint64_t* acci, int lane)
{
#pragma unroll
    for (int j = 0; j < S; j++) {
        float rr = lo2(accr[j]) + hi2(accr[j]);
        float ii = lo2(acci[j]) + hi2(acci[j]);
#pragma unroll
        for (int o = 16; o > 0; o >>= 1) {
            rr += __shfl_xor_sync(0xFFFFFFFFu, rr, o);
            ii += __shfl_xor_sync(0xFFFFFFFFu, ii, o);
        }
        if (lane == 0) powdst[4 * j] = rr * rr + ii * ii;
    }
}

// ---------------------------------------------------------------------------
// Two residue classes per warp (unchanged, proven).
// ---------------------------------------------------------------------------
template <int PARITY>
static __device__ __forceinline__ void do_class2(
    const float* br, const float* bi,   // smem, 3264 floats each
    int n0, int lane, float* powrow)
{
    constexpr int SA   = 5;
    constexpr int SB   = (PARITY == 0) ? 6 : 5;
    constexpr int DMA  = (PARITY == 0) ? -8  : -7;
    constexpr int DMB  = (PARITY == 0) ? -10 : -9;
    constexpr int OFFA = DMA + 10;   // 2 or 3
    constexpr int OFFB = DMB + 10;   // 0 or 1

    const int p0 = 2 * lane;     // packed pair (p0, p0+1); stride 64/iter
    const int fA = n0 + DMA;
    const int fB = n0 + DMB;

    float2 ea = phasor(modL(fA * p0)), eb = phasor(modL(fA * (p0 + 1)));
    uint64_t sAr = pk2(ea.x, eb.x), sAi = pk2(ea.y, eb.y);
    ea = phasor(modL(fB * p0)); eb = phasor(modL(fB * (p0 + 1)));
    uint64_t sBr = pk2(ea.x, eb.x), sBi = pk2(ea.y, eb.y);

    float2 st = phasor(modL(fA * 64));
    uint64_t stAr = splat(st.x), stAi = splat(st.y);
    st = phasor(modL(fB * 64));
    uint64_t stBr = splat(st.x), stBi = splat(st.y);

    float2 pa = phasor(4 * p0), pb = phasor(4 * p0 + 4);
    uint64_t phir = pk2(pa.x, pb.x), phii = pk2(pa.y, pb.y);
    float2 psc = phasor(256);
    uint64_t pstr = splat(psc.x), psti = splat(psc.y);

    uint64_t aAr[SA], aAi[SA], aBr[SB], aBi[SB];
#pragma unroll
    for (int j = 0; j < SA; j++) { aAr[j] = aAi[j] = 0ULL; }
#pragma unroll
    for (int j = 0; j < SB; j++) { aBr[j] = aBi[j] = 0ULL; }

    int p = p0;
#pragma unroll 1
    for (int it = 0; it < 13; ++it, p += 64) {
        const bool v = (p < PDIM);
        uint64_t xr0 = v ? *(const uint64_t*)(br + p)            : 0ULL;
        uint64_t xr1 = v ? *(const uint64_t*)(br + p + PDIM)     : 0ULL;
        uint64_t xr2 = v ? *(const uint64_t*)(br + p + 2 * PDIM) : 0ULL;
        uint64_t xr3 = v ? *(const uint64_t*)(br + p + 3 * PDIM) : 0ULL;
        uint64_t xi0 = v ? *(const uint64_t*)(bi + p)            : 0ULL;
        uint64_t xi1 = v ? *(const uint64_t*)(bi + p + PDIM)     : 0ULL;
        uint64_t xi2 = v ? *(const uint64_t*)(bi + p + 2 * PDIM) : 0ULL;
        uint64_t xi3 = v ? *(const uint64_t*)(bi + p + 3 * PDIM) : 0ULL;

        uint64_t WAr, WAi, WBr, WBi;
        if (PARITY == 0) {
            uint64_t t0r, t0i, t2r, t2i;
            F2ADD(t0r, xr0, xr2); F2ADD(t0i, xi0, xi2);
            F2ADD(t2r, xr1, xr3); F2ADD(t2i, xi1, xi3);
            F2ADD(WAr, t0r, t2r); F2ADD(WAi, t0i, t2i);
            uint64_t n1 = t2r ^ SGNMASK, n2 = t2i ^ SGNMASK;
            F2ADD(WBr, t0r, n1);  F2ADD(WBi, t0i, n2);
        } else {
            uint64_t nr2 = xr2 ^ SGNMASK, ni2 = xi2 ^ SGNMASK;
            uint64_t nr3 = xr3 ^ SGNMASK, ni3 = xi3 ^ SGNMASK;
            uint64_t t1r, t1i, t3r, t3i;
            F2ADD(t1r, xr0, nr2); F2ADD(t1i, xi0, ni2);
            F2ADD(t3r, xr1, nr3); F2ADD(t3i, xi1, ni3);
            uint64_t nt3i = t3i ^ SGNMASK, nt3r = t3r ^ SGNMASK;
            F2ADD(WAr, t1r, nt3i); F2ADD(WAi, t1i, t3r);
            F2ADD(WBr, t1r, t3i);  F2ADD(WBi, t1i, nt3r);
        }

        uint64_t tc, ntc;
        F2ADD(tc, phir, phir);
        ntc = tc ^ SGNMASK;

        eval_cheb<SA>(WAr, WAi, sAr, sAi, phir, phii, tc, ntc, aAr, aAi);
        eval_cheb<SB>(WBr, WBi, sBr, sBi, phir, phii, tc, ntc, aBr, aBi);

        CMUL(sAr, sAi, stAr, stAi);
        CMUL(sBr, sBi, stBr, stBi);
        CMUL(phir, phii, pstr, psti);
    }

    reduce_pows<SA>(powrow + OFFA, aAr, aAi, lane);
    reduce_pows<SB>(powrow + OFFB, aBr, aBi, lane);
}

// ---------------------------------------------------------------------------
// k_main: TMA-bulk slice -> smem; phase A + argmax + phase B; prestores
//   g_trig[sb] = (phasor(mm), phasor(tt)) for k_final.
// ---------------------------------------------------------------------------
__global__ void __launch_bounds__(256)
k_main(const float* __restrict__ lsr, const float* __restrict__ lsi,
       const int* __restrict__ cs) {
    extern __shared__ float smbuf[];          // [(a*2+c) * SL], 104448 B
    __shared__ uint64_t mbar[AA];
    __shared__ float    spow[AA][NOFF];
    __shared__ float    shpow[NOFF];
    __shared__ int      sh_mm;

    const int sb   = blockIdx.x;
    const int s    = sb / BB;
    const int w    = threadIdx.x >> 5;
    const int lane = threadIdx.x & 31;

    const int ideal = ((KK - cs[s]) % KK) * LPK;   // in [0,SL), multiple of 4

    if (threadIdx.x == 0) {
#pragma unroll
        for (int a = 0; a < AA; a++) MBAR_INIT(smem_u32(&mbar[a]), 1);
    }
    __syncthreads();
    if (threadIdx.x == 0) {
#pragma unroll
        for (int a = 0; a < AA; a++) {
            uint32_t mb = smem_u32(&mbar[a]);
            MBAR_EXPECT_TX(mb, 2 * SL * 4);
            const float* srcr = lsr + ((size_t)sb * AA + a) * SL;
            const float* srci = lsi + ((size_t)sb * AA + a) * SL;
            TMA_BULK_G2S(smem_u32(smbuf + (a * 2) * SL),     srcr, SL * 4, mb);
            TMA_BULK_G2S(smem_u32(smbuf + (a * 2 + 1) * SL), srci, SL * 4, mb);
        }
    }

    // ---- phase A: one double-class job per warp ----
    const int a      = w >> 1;
    const int parity = w & 1;
    mbar_wait0(smem_u32(&mbar[a]));
    {
        const float* br = smbuf + (a * 2) * SL;
        const float* bi = smbuf + (a * 2 + 1) * SL;
        if (parity == 0) do_class2<0>(br, bi, ideal, lane, &spow[a][0]);
        else             do_class2<1>(br, bi, ideal, lane, &spow[a][0]);
    }
    __syncthreads();

    // ---- argmax over candidates (first-max tie rule) ----
    if (threadIdx.x < NOFF) {
        int d = threadIdx.x;
        shpow[d] = spow[0][d] + spow[1][d] + spow[2][d] + spow[3][d];
    }
    __syncthreads();
    if (threadIdx.x == 0) {
        int   best = 0;
        float bp   = shpow[0];
        for (int j = 1; j < NOFF; j++)
            if (shpow[j] > bp) { bp = shpow[j]; best = j; }
        int toff = best - 10;
        int mmv  = modL(toff + ideal);
        int ttv  = modL(toff);
        g_m[sb]  = mmv;
        g_tt[sb] = ttv;
        float2 msv0 = phasor(mmv);
        float2 tsv0 = phasor(ttv);
        g_trig[sb] = make_float4(msv0.x, msv0.y, tsv0.x, tsv0.y);
        sh_mm    = mmv;
    }
    __syncthreads();

    // ---- phase B: OCC averaging from SMEM ----
    const int mmv = sh_mm;
    float2 msv = phasor(mmv);                        // e^{i th mm}
    float2 spv = phasor((mmv * 1024) % SL);          // r += 256 step
    float2 sd0 = phasor((mmv * 4 * (int)threadIdx.x) % SL);

#pragma unroll
    for (int aa = 0; aa < AA; aa++) {
        const float* br2 = smbuf + (aa * 2) * SL;
        const float* bi2 = smbuf + (aa * 2 + 1) * SL;
        float2* ho = g_havg + ((size_t)sb * AA + aa) * RR;
        float pc = sd0.x, ps = sd0.y;
        for (int r = threadIdx.x; r < RR; r += 256) {
            int l0 = 4 * r;
            float4 xr = *(const float4*)(br2 + l0);
            float4 xi = *(const float4*)(bi2 + l0);
            float xrv[4] = {xr.x, xr.y, xr.z, xr.w};
            float xiv[4] = {xi.x, xi.y, xi.z, xi.w};
            float qc = pc, qs = ps;
            float sr = 0.0f, si = 0.0f;
#pragma unroll
            for (int j = 0; j < 4; j++) {
                sr += xrv[j] * qc - xiv[j] * qs;
                si += xrv[j] * qs + xiv[j] * qc;
                if (j < 3) {
                    float nc = qc * msv.x - qs * msv.y;
                    float ns = qc * msv.y + qs * msv.x;
                    qc = nc; qs = ns;
                }
            }
            ho[r] = make_float2(sr * 0.25f, si * 0.25f);
            float nc = pc * spv.x - ps * spv.y;
            float ns = pc * spv.y + ps * spv.x;
            pc = nc; ps = ns;
        }
    }
}

// ---------------------------------------------------------------------------
// k_final: warp-per-stream over a 128-l tile for one (b,a); 4 l's per thread.
//   ms/ts from g_trig; residual float4-vectorized; regs pinned to 32 via
//   __launch_bounds__(256, 8) so occupancy stays at the R11 level.
// ---------------------------------------------------------------------------
__global__ void __launch_bounds__(256, 8)
k_final(const float* __restrict__ lsr, const float* __restrict__ lsi,
        float* __restrict__ out) {
    const int blk  = blockIdx.x;
    const int ba   = blk / NTILE;
    const int tile = blk % NTILE;
    const int a    = ba % AA;
    const int b    = ba / AA;
    const int s    = threadIdx.x >> 5;   // warp = stream
    const int lane = threadIdx.x & 31;

    const int lbase = tile * TILE;
    const int l0    = lbase + lane * 4;
    const bool act  = (l0 < SL);

    __shared__ float shc[SS][2 * TILE];   // recon contributions
    __shared__ float shres[2 * TILE];     // residual

    const int sb = s * BB + b;
    const int mm = g_m[sb];
    const int tt = g_tt[sb];
    const float4 tg = g_trig[sb];        // (ms.x, ms.y, ts.x, ts.y)
    const float2* hv = g_havg + ((size_t)sb * AA + a) * RR;

    float hr[4], hi[4], pr[4], pi[4];

    if (act) {
        int g = l0 >> 2;
        float2 hm = hv[max(g - 1, 0)];
        float2 h0 = hv[g];
        float2 hp = hv[min(g + 1, RR - 1)];

        float f0 = (g > 0)      ? 0.625f : 0.0f;
        float f1 = (g > 0)      ? 0.875f : 0.0f;
        float f2 = (g < RR - 1) ? 0.125f : 0.0f;
        float f3 = (g < RR - 1) ? 0.375f : 0.0f;

        hr[0] = hm.x * (1.0f - f0) + h0.x * f0;  hi[0] = hm.y * (1.0f - f0) + h0.y * f0;
        hr[1] = hm.x * (1.0f - f1) + h0.x * f1;  hi[1] = hm.y * (1.0f - f1) + h0.y * f1;
        hr[2] = h0.x * (1.0f - f2) + hp.x * f2;  hi[2] = h0.y * (1.0f - f2) + hp.y * f2;
        hr[3] = h0.x * (1.0f - f3) + hp.x * f3;  hi[3] = h0.y * (1.0f - f3) + hp.y * f3;

        // mm*l0 <= 3263*3263 ~ 10.6M: int32-safe
        float2 pm = phasor((mm * l0) % SL);
        float pmc = pm.x, pms = pm.y;

        float cr[4], cc[4];
#pragma unroll
        for (int j = 0; j < 4; j++) {
            pr[j] = pmc; pi[j] = pms;
            cr[j] = hr[j] * pmc + hi[j] * pms;   // h_interp * conj(ph_m)
            cc[j] = hi[j] * pmc - hr[j] * pms;
            if (j < 3) {
                float nc = pmc * tg.x - pms * tg.y;
                float ns = pmc * tg.y + pms * tg.x;
                pmc = nc; pms = ns;
            }
        }
        float4* dst = (float4*)&shc[s][lane * 8];
        dst[0] = make_float4(cr[0], cc[0], cr[1], cc[1]);
        dst[1] = make_float4(cr[2], cc[2], cr[3], cc[3]);
    }
    __syncthreads();

    // residual reduction: 64 threads x float4 chunk of the 256-float tile
    if (threadIdx.x < TILE / 2) {
        const int t  = threadIdx.x;
        const int lg = lbase + t * 2;     // covers l = lg, lg+1
        if (lg < SL) {
            float4 sum = make_float4(0.f, 0.f, 0.f, 0.f);
#pragma unroll
            for (int ss2 = 0; ss2 < SS; ss2++) {
                float4 v = *(const float4*)&shc[ss2][t * 4];
                sum.x += v.x; sum.y += v.y; sum.z += v.z; sum.w += v.w;
            }
            float2 glr = *(const float2*)(lsr + (size_t)ba * SL + lg);
            float2 gli = *(const float2*)(lsi + (size_t)ba * SL + lg);
            *(float4*)&shres[t * 4] = make_float4(
                glr.x - sum.x, gli.x - sum.y, glr.y - sum.z, gli.y - sum.w);
        }
    }
    __syncthreads();

    if (act) {
        float2 pt = phasor((tt * l0) % SL);
        float ptc = pt.x, pts = pt.y;

        float4 r01 = *(float4*)&shres[lane * 8];
        float4 r23 = *(float4*)&shres[lane * 8 + 4];
        float rres[4] = {r01.x, r01.z, r23.x, r23.z};
        float rims[4] = {r01.y, r01.w, r23.y, r23.w};

        float4 outr, outi;
        float* orp = &outr.x;
        float* oip = &outi.x;
#pragma unroll
        for (int j = 0; j < 4; j++) {
            float wr = hr[j] + rres[j] * pr[j] - rims[j] * pi[j];
            float wi = hi[j] + rres[j] * pi[j] + rims[j] * pr[j];
            orp[j] = wr * ptc + wi * pts;
            oip[j] = wi * ptc - wr * pts;
            if (j < 3) {
                float nc = ptc * tg.z - pts * tg.w;
                float ns = ptc * tg.w + pts * tg.z;
                ptc = nc; pts = ns;
            }
        }

        const size_t TOT = (size_t)SS * BB * AA * SL;
        size_t off = ((size_t)sb * AA + a) * SL + (size_t)l0;
        *(float4*)(out + off)       = outr;
        *(float4*)(out + TOT + off) = outi;
    }
}

// ---------------------------------------------------------------------------
extern "C" void kernel_launch(void* const* d_in, const int* in_sizes, int n_in,
                              void* d_out, int out_size) {
    (void)in_sizes; (void)n_in; (void)out_size;
    const float* lsr = (const float*)d_in[0];
    const float* lsi = (const float*)d_in[1];
    const int*   cs  = (const int*)d_in[2];
    float*       out = (float*)d_out;

    cudaFuncSetAttribute(k_main, cudaFuncAttributeMaxDynamicSharedMemorySize, SMEM_DYN);

    k_main<<<SS * BB, 256, SMEM_DYN>>>(lsr, lsi, cs);
    k_final<<<BB * AA * NTILE, 256>>>(lsr, lsi, out);
}

// round 15
// speedup vs baseline: 1.0798x; 1.0798x over previous
#include <cuda_runtime.h>
#include <cstdint>

#define SL   3264            // seq length L
#define KK   12
#define LPK  (SL / KK)       // 272
#define SS   8               // streams
#define BB   64              // batch
#define AA   4               // antennas
#define RR   (SL / 4)        // 816 (L / LOCC)
#define NOFF 21              // delay candidates -10..10
#define TILE 128             // l-tile for k_final
#define NTILE 26             // ceil(3264/128)
#define PDIM 816             // decimated length L/4

#define SMEM_DYN (AA * 2 * SL * 4)   // 104448 B

// ---- scratch (device-global: allocation-free contract) ----
__device__ int    g_m[SS * BB];                   // (t_off + ideal_peak) mod L
__device__ int    g_tt[SS * BB];                  // t_off mod L
__device__ float2 g_msv[SS * BB];                 // e^{i th mm}
__device__ float2 g_tsv[SS * BB];                 // e^{i th tt}
__device__ float2 g_havg[SS * BB * AA * RR];      // OCC-averaged channel, 13.4 MB

// ---- packed f32x2 helpers (sm_103a dual-lane fp32) ----
#define F2MUL(o, a, b)    asm("mul.rn.f32x2 %0, %1, %2;"      : "=l"(o) : "l"(a), "l"(b))
#define F2FMA(o, a, b, c) asm("fma.rn.f32x2 %0, %1, %2, %3;"  : "=l"(o) : "l"(a), "l"(b), "l"(c))
#define F2ADD(o, a, b)    asm("add.rn.f32x2 %0, %1, %2;"      : "=l"(o) : "l"(a), "l"(b))
#define SGNMASK 0x8000000080000000ULL

static __device__ __forceinline__ uint64_t pk2(float lo, float hi) {
    uint64_t r; asm("mov.b64 %0, {%1, %2};" : "=l"(r) : "f"(lo), "f"(hi)); return r;
}
static __device__ __forceinline__ float lo2(uint64_t v) {
    float a, b; asm("mov.b64 {%0, %1}, %2;" : "=f"(a), "=f"(b) : "l"(v)); return a;
}
static __device__ __forceinline__ float hi2(uint64_t v) {
    float a, b; asm("mov.b64 {%0, %1}, %2;" : "=f"(a), "=f"(b) : "l"(v)); return b;
}
static __device__ __forceinline__ uint64_t splat(float v) { return pk2(v, v); }

// fp32 2*pi/L, matching reference fp32 angle math
#define WF ((float)(6.283185307179586476925286766559 / 3264.0))

// fast phasor: e^{i th k}; reduce to (-pi, pi] for MUFU accuracy
static __device__ __forceinline__ float2 phasor(int k) {
    if (k > SL / 2) k -= SL;
    float s, c;
    __sincosf(WF * (float)k, &s, &c);
    return make_float2(c, s);
}

static __device__ __forceinline__ int modL(int x) { x %= SL; return x < 0 ? x + SL : x; }

// packed complex in-place multiply: (ar,ai) *= (br,bi)
#define CMUL(ar, ai, br, bi) do {            \
    uint64_t _m, _nr;                        \
    F2MUL(_m, ai, bi); _m ^= SGNMASK;        \
    F2FMA(_nr, ar, br, _m);                  \
    F2MUL(_m, ai, br);                       \
    F2FMA(ai, ar, bi, _m);                   \
    ar = _nr;                                \
} while (0)

// ---- mbarrier / TMA-bulk helpers ----
static __device__ __forceinline__ uint32_t smem_u32(const void* p) {
    uint32_t r;
    asm("{ .reg .u64 t; cvta.to.shared.u64 t, %1; cvt.u32.u64 %0, t; }" : "=r"(r) : "l"(p));
    return r;
}
#define MBAR_INIT(addr, cnt) \
    asm volatile("mbarrier.init.shared.b64 [%0], %1;" :: "r"(addr), "r"(cnt) : "memory")
#define MBAR_EXPECT_TX(addr, bytes) \
    asm volatile("mbarrier.arrive.expect_tx.shared.b64 _, [%0], %1;" :: "r"(addr), "r"(bytes) : "memory")
#define TMA_BULK_G2S(dst, src, bytes, mbar) \
    asm volatile("cp.async.bulk.shared::cta.global.mbarrier::complete_tx::bytes [%0], [%1], %2, [%3];" \
        :: "r"(dst), "l"(src), "r"(bytes), "r"(mbar) : "memory")
static __device__ __forceinline__ void mbar_wait0(uint32_t addr) {
    asm volatile(
        "{\n\t"
        ".reg .pred P;\n\t"
        "WAIT_%=:\n\t"
        "mbarrier.try_wait.parity.acquire.cta.shared::cta.b64 P, [%0], 0, 0x989680;\n\t"
        "@P bra.uni DONE_%=;\n\t"
        "bra.uni WAIT_%=;\n\t"
        "DONE_%=:\n\t"
        "}" :: "r"(addr) : "memory");
}

// ---------------------------------------------------------------------------
// Chebyshev accumulation chunk for one class (proven).
// ---------------------------------------------------------------------------
template <int S>
static __device__ __forceinline__ void eval_cheb(
    uint64_t Wr, uint64_t Wi, uint64_t sr, uint64_t si,
    uint64_t phir, uint64_t phii, uint64_t tc, uint64_t ntc,
    uint64_t* accr, uint64_t* acci)
{
    uint64_t m, v0r, v0i;
    F2MUL(m, Wi, si); m ^= SGNMASK;
    F2FMA(v0r, Wr, sr, m);
    F2MUL(m, Wi, sr);
    F2FMA(v0i, Wr, si, m);
    F2ADD(accr[0], accr[0], v0r);
    F2ADD(acci[0], acci[0], v0i);

    uint64_t v1r, v1i;
    F2MUL(m, v0i, phii); m ^= SGNMASK;
    F2FMA(v1r, v0r, phir, m);
    F2MUL(m, v0i, phir);
    F2FMA(v1i, v0r, phii, m);
    F2ADD(accr[1], accr[1], v1r);
    F2ADD(acci[1], acci[1], v1i);

    uint64_t pr = v0r, pi_ = v0i, cr = v1r, ci_ = v1i;
#pragma unroll
    for (int j = 2; j < S; j++) {
        uint64_t co = (j & 1) ? tc : ntc;
        uint64_t nr, ni;
        F2FMA(nr, co, cr, pr);
        F2FMA(ni, co, ci_, pi_);
        pr = cr; pi_ = ci_; cr = nr; ci_ = ni;
        F2ADD(accr[j], accr[j], nr);
        F2ADD(acci[j], acci[j], ni);
    }
}

// warp-reduce packed complex, lane0 writes |X|^2
template <int S>
static __device__ __forceinline__ void reduce_pows(
    float* powdst /*stride-4*/, const uint64_t* accr, const uint64_t* acci, int lane)
{
#pragma unroll
    for (int j = 0; j < S; j++) {
        float rr = lo2(accr[j]) + hi2(accr[j]);
        float ii = lo2(acci[j]) + hi2(acci[j]);
#pragma unroll
        for (int o = 16; o > 0; o >>= 1) {
            rr += __shfl_xor_sync(0xFFFFFFFFu, rr, o);
            ii += __shfl_xor_sync(0xFFFFFFFFu, ii, o);
        }
        if (lane == 0) powdst[4 * j] = rr * rr + ii * ii;
    }
}

// ---------------------------------------------------------------------------
// Two residue classes per warp; 12 clean iterations + 1 predicated tail.
//   PARITY 0: class0 (S=5, dmin=-8, slot+2) and class2 (S=6, dmin=-10, slot+0)
//   PARITY 1: class1 (S=5, dmin=-7, slot+3) and class3 (S=5, dmin=-9, slot+1)
// ---------------------------------------------------------------------------
template <int PARITY>
static __device__ __forceinline__ void do_class2(
    const float* br, const float* bi,   // smem, 3264 floats each
    int n0, int lane, float* powrow)
{
    constexpr int SA   = 5;
    constexpr int SB   = (PARITY == 0) ? 6 : 5;
    constexpr int DMA  = (PARITY == 0) ? -8  : -7;
    constexpr int DMB  = (PARITY == 0) ? -10 : -9;
    constexpr int OFFA = DMA + 10;   // 2 or 3
    constexpr int OFFB = DMB + 10;   // 0 or 1

    const int p0 = 2 * lane;     // packed pair (p0, p0+1); stride 64/iter
    const int fA = n0 + DMA;
    const int fB = n0 + DMB;

    float2 ea = phasor(modL(fA * p0)), eb = phasor(modL(fA * (p0 + 1)));
    uint64_t sAr = pk2(ea.x, eb.x), sAi = pk2(ea.y, eb.y);
    ea = phasor(modL(fB * p0)); eb = phasor(modL(fB * (p0 + 1)));
    uint64_t sBr = pk2(ea.x, eb.x), sBi = pk2(ea.y, eb.y);

    float2 st = phasor(modL(fA * 64));
    uint64_t stAr = splat(st.x), stAi = splat(st.y);
    st = phasor(modL(fB * 64));
    uint64_t stBr = splat(st.x), stBi = splat(st.y);

    float2 pa = phasor(4 * p0), pb = phasor(4 * p0 + 4);
    uint64_t phir = pk2(pa.x, pb.x), phii = pk2(pa.y, pb.y);
    float2 psc = phasor(256);
    uint64_t pstr = splat(psc.x), psti = splat(psc.y);

    uint64_t aAr[SA], aAi[SA], aBr[SB], aBi[SB];
#pragma unroll
    for (int j = 0; j < SA; j++) { aAr[j] = aAi[j] = 0ULL; }
#pragma unroll
    for (int j = 0; j < SB; j++) { aBr[j] = aBi[j] = 0ULL; }

    int p = p0;
#pragma unroll 1
    for (int it = 0; it < 13; ++it, p += 64) {
        uint64_t xr0, xr1, xr2, xr3, xi0, xi1, xi2, xi3;
        if (it < 12) {          // p = p0 + it*64 <= 62 + 11*64 = 766 < 816
            xr0 = *(const uint64_t*)(br + p);
            xr1 = *(const uint64_t*)(br + p + PDIM);
            xr2 = *(const uint64_t*)(br + p + 2 * PDIM);
            xr3 = *(const uint64_t*)(br + p + 3 * PDIM);
            xi0 = *(const uint64_t*)(bi + p);
            xi1 = *(const uint64_t*)(bi + p + PDIM);
            xi2 = *(const uint64_t*)(bi + p + 2 * PDIM);
            xi3 = *(const uint64_t*)(bi + p + 3 * PDIM);
        } else {                // tail: valid only for p < PDIM (lane < 24)
            const bool v = (p < PDIM);
            xr0 = v ? *(const uint64_t*)(br + p)            : 0ULL;
            xr1 = v ? *(const uint64_t*)(br + p + PDIM)     : 0ULL;
            xr2 = v ? *(const uint64_t*)(br + p + 2 * PDIM) : 0ULL;
            xr3 = v ? *(const uint64_t*)(br + p + 3 * PDIM) : 0ULL;
            xi0 = v ? *(const uint64_t*)(bi + p)            : 0ULL;
            xi1 = v ? *(const uint64_t*)(bi + p + PDIM)     : 0ULL;
            xi2 = v ? *(const uint64_t*)(bi + p + 2 * PDIM) : 0ULL;
            xi3 = v ? *(const uint64_t*)(bi + p + 3 * PDIM) : 0ULL;
        }

        uint64_t WAr, WAi, WBr, WBi;
        if (PARITY == 0) {
            uint64_t t0r, t0i, t2r, t2i;
            F2ADD(t0r, xr0, xr2); F2ADD(t0i, xi0, xi2);
            F2ADD(t2r, xr1, xr3); F2ADD(t2i, xi1, xi3);
            F2ADD(WAr, t0r, t2r); F2ADD(WAi, t0i, t2i);
            uint64_t n1 = t2r ^ SGNMASK, n2 = t2i ^ SGNMASK;
            F2ADD(WBr, t0r, n1);  F2ADD(WBi, t0i, n2);
        } else {
            uint64_t nr2 = xr2 ^ SGNMASK, ni2 = xi2 ^ SGNMASK;
            uint64_t nr3 = xr3 ^ SGNMASK, ni3 = xi3 ^ SGNMASK;
            uint64_t t1r, t1i, t3r, t3i;
            F2ADD(t1r, xr0, nr2); F2ADD(t1i, xi0, ni2);
            F2ADD(t3r, xr1, nr3); F2ADD(t3i, xi1, ni3);
            uint64_t nt3i = t3i ^ SGNMASK, nt3r = t3r ^ SGNMASK;
            F2ADD(WAr, t1r, nt3i); F2ADD(WAi, t1i, t3r);
            F2ADD(WBr, t1r, t3i);  F2ADD(WBi, t1i, nt3r);
        }

        uint64_t tc, ntc;
        F2ADD(tc, phir, phir);
        ntc = tc ^ SGNMASK;

        eval_cheb<SA>(WAr, WAi, sAr, sAi, phir, phii, tc, ntc, aAr, aAi);
        eval_cheb<SB>(WBr, WBi, sBr, sBi, phir, phii, tc, ntc, aBr, aBi);

        CMUL(sAr, sAi, stAr, stAi);
        CMUL(sBr, sBi, stBr, stBi);
        CMUL(phir, phii, pstr, psti);
    }

    reduce_pows<SA>(powrow + OFFA, aAr, aAi, lane);
    reduce_pows<SB>(powrow + OFFB, aBr, aBi, lane);
}

// ---------------------------------------------------------------------------
// k_main: TMA-bulk slice -> smem; phase A + argmax + phase B; prestores
//   g_msv/g_tsv step phasors for k_final.
// ---------------------------------------------------------------------------
__global__ void __launch_bounds__(256)
k_main(const float* __restrict__ lsr, const float* __restrict__ lsi,
       const int* __restrict__ cs) {
    extern __shared__ float smbuf[];          // [(a*2+c) * SL], 104448 B
    __shared__ uint64_t mbar[AA];
    __shared__ float    spow[AA][NOFF];
    __shared__ float    shpow[NOFF];
    __shared__ int      sh_mm;

    const int sb   = blockIdx.x;
    const int s    = sb / BB;
    const int w    = threadIdx.x >> 5;
    const int lane = threadIdx.x & 31;

    const int ideal = ((KK - cs[s]) % KK) * LPK;   // in [0,SL), multiple of 4

    if (threadIdx.x == 0) {
#pragma unroll
        for (int a = 0; a < AA; a++) MBAR_INIT(smem_u32(&mbar[a]), 1);
    }
    __syncthreads();
    if (threadIdx.x == 0) {
#pragma unroll
        for (int a = 0; a < AA; a++) {
            uint32_t mb = smem_u32(&mbar[a]);
            MBAR_EXPECT_TX(mb, 2 * SL * 4);
            const float* srcr = lsr + ((size_t)sb * AA + a) * SL;
            const float* srci = lsi + ((size_t)sb * AA + a) * SL;
            TMA_BULK_G2S(smem_u32(smbuf + (a * 2) * SL),     srcr, SL * 4, mb);
            TMA_BULK_G2S(smem_u32(smbuf + (a * 2 + 1) * SL), srci, SL * 4, mb);
        }
    }

    // ---- phase A: one double-class job per warp ----
    const int a      = w >> 1;
    const int parity = w & 1;
    mbar_wait0(smem_u32(&mbar[a]));
    {
        const float* br = smbuf + (a * 2) * SL;
        const float* bi = smbuf + (a * 2 + 1) * SL;
        if (parity == 0) do_class2<0>(br, bi, ideal, lane, &spow[a][0]);
        else             do_class2<1>(br, bi, ideal, lane, &spow[a][0]);
    }
    __syncthreads();

    // ---- argmax over candidates (first-max tie rule) ----
    if (threadIdx.x < NOFF) {
        int d = threadIdx.x;
        shpow[d] = spow[0][d] + spow[1][d] + spow[2][d] + spow[3][d];
    }
    __syncthreads();
    if (threadIdx.x == 0) {
        int   best = 0;
        float bp   = shpow[0];
        for (int j = 1; j < NOFF; j++)
            if (shpow[j] > bp) { bp = shpow[j]; best = j; }
        int toff = best - 10;
        int mmv  = modL(toff + ideal);
        int ttv  = modL(toff);
        g_m[sb]   = mmv;
        g_tt[sb]  = ttv;
        g_msv[sb] = phasor(mmv);
        g_tsv[sb] = phasor(ttv);
        sh_mm     = mmv;
    }
    __syncthreads();

    // ---- phase B: OCC averaging from SMEM ----
    const int mmv = sh_mm;
    float2 msv = phasor(mmv);                        // e^{i th mm}
    float2 spv = phasor((mmv * 1024) % SL);          // r += 256 step
    float2 sd0 = phasor((mmv * 4 * (int)threadIdx.x) % SL);

#pragma unroll
    for (int aa = 0; aa < AA; aa++) {
        const float* br2 = smbuf + (aa * 2) * SL;
        const float* bi2 = smbuf + (aa * 2 + 1) * SL;
        float2* ho = g_havg + ((size_t)sb * AA + aa) * RR;
        float pc = sd0.x, ps = sd0.y;
        for (int r = threadIdx.x; r < RR; r += 256) {
            int l0 = 4 * r;
            float4 xr = *(const float4*)(br2 + l0);
            float4 xi = *(const float4*)(bi2 + l0);
            float xrv[4] = {xr.x, xr.y, xr.z, xr.w};
            float xiv[4] = {xi.x, xi.y, xi.z, xi.w};
            float qc = pc, qs = ps;
            float sr = 0.0f, si = 0.0f;
#pragma unroll
            for (int j = 0; j < 4; j++) {
                sr += xrv[j] * qc - xiv[j] * qs;
                si += xrv[j] * qs + xiv[j] * qc;
                if (j < 3) {
                    float nc = qc * msv.x - qs * msv.y;
                    float ns = qc * msv.y + qs * msv.x;
                    qc = nc; qs = ns;
                }
            }
            ho[r] = make_float2(sr * 0.25f, si * 0.25f);
            float nc = pc * spv.x - ps * spv.y;
            float ns = pc * spv.y + ps * spv.x;
            pc = nc; ps = ns;
        }
    }
}

// ---------------------------------------------------------------------------
// k_final: warp-per-stream over a 128-l tile for one (b,a); 4 l's per thread.
//   Identical to R11 except ms/ts step phasors loaded from g_msv/g_tsv.
// ---------------------------------------------------------------------------
__global__ void __launch_bounds__(256)
k_final(const float* __restrict__ lsr, const float* __restrict__ lsi,
        float* __restrict__ out) {
    const int blk  = blockIdx.x;
    const int ba   = blk / NTILE;
    const int tile = blk % NTILE;
    const int a    = ba % AA;
    const int b    = ba / AA;
    const int s    = threadIdx.x >> 5;   // warp = stream
    const int lane = threadIdx.x & 31;

    const int lbase = tile * TILE;
    const int l0    = lbase + lane * 4;
    const bool act  = (l0 < SL);

    __shared__ float shc[SS][2 * TILE];   // recon contributions
    __shared__ float shres[2 * TILE];     // residual

    const int sb = s * BB + b;
    const int mm = g_m[sb];
    const int tt = g_tt[sb];
    const float2* hv = g_havg + ((size_t)sb * AA + a) * RR;

    float hr[4], hi[4], pr[4], pi[4];

    if (act) {
        int g = l0 >> 2;
        float2 hm = hv[max(g - 1, 0)];
        float2 h0 = hv[g];
        float2 hp = hv[min(g + 1, RR - 1)];

        float f0 = (g > 0)      ? 0.625f : 0.0f;
        float f1 = (g > 0)      ? 0.875f : 0.0f;
        float f2 = (g < RR - 1) ? 0.125f : 0.0f;
        float f3 = (g < RR - 1) ? 0.375f : 0.0f;

        hr[0] = hm.x * (1.0f - f0) + h0.x * f0;  hi[0] = hm.y * (1.0f - f0) + h0.y * f0;
        hr[1] = hm.x * (1.0f - f1) + h0.x * f1;  hi[1] = hm.y * (1.0f - f1) + h0.y * f1;
        hr[2] = h0.x * (1.0f - f2) + hp.x * f2;  hi[2] = h0.y * (1.0f - f2) + hp.y * f2;
        hr[3] = h0.x * (1.0f - f3) + hp.x * f3;  hi[3] = h0.y * (1.0f - f3) + hp.y * f3;

        // mm*l0 <= 3263*3263 ~ 10.6M: int32-safe
        float2 pm = phasor((mm * l0) % SL);
        float2 ms = g_msv[sb];
        float pmc = pm.x, pms = pm.y;

        float cr[4], cc[4];
#pragma unroll
        for (int j = 0; j < 4; j++) {
            pr[j] = pmc; pi[j] = pms;
            cr[j] = hr[j] * pmc + hi[j] * pms;   // h_interp * conj(ph_m)
            cc[j] = hi[j] * pmc - hr[j] * pms;
            if (j < 3) {
                float nc = pmc * ms.x - pms * ms.y;
                float ns = pmc * ms.y + pms * ms.x;
                pmc = nc; pms = ns;
            }
        }
        float4* dst = (float4*)&shc[s][lane * 8];
        dst[0] = make_float4(cr[0], cc[0], cr[1], cc[1]);
        dst[1] = make_float4(cr[2], cc[2], cr[3], cc[3]);
    }
    __syncthreads();

    // residual reduction (R11 layout)
    {
        int ll   = threadIdx.x >> 1;
        int comp = threadIdx.x & 1;
        int lg   = lbase + ll;
        if (lg < SL) {
            float sum = 0.0f;
#pragma unroll
            for (int ss2 = 0; ss2 < SS; ss2++) sum += shc[ss2][ll * 2 + comp];
            const float* ls0 = comp ? lsi : lsr;
            shres[ll * 2 + comp] = ls0[(size_t)ba * SL + lg] - sum;
        }
    }
    __syncthreads();

    if (act) {
        float2 pt = phasor((tt * l0) % SL);
        float2 ts = g_tsv[sb];
        float ptc = pt.x, pts = pt.y;

        float4 r01 = *(float4*)&shres[lane * 8];
        float4 r23 = *(float4*)&shres[lane * 8 + 4];
        float rres[4] = {r01.x, r01.z, r23.x, r23.z};
        float rims[4] = {r01.y, r01.w, r23.y, r23.w};

        float4 outr, outi;
        float* orp = &outr.x;
        float* oip = &outi.x;
#pragma unroll
        for (int j = 0; j < 4; j++) {
            float wr = hr[j] + rres[j] * pr[j] - rims[j] * pi[j];
            float wi = hi[j] + rres[j] * pi[j] + rims[j] * pr[j];
            orp[j] = wr * ptc + wi * pts;
            oip[j] = wi * ptc - wr * pts;
            if (j < 3) {
                float nc = ptc * ts.x - pts * ts.y;
                float ns = ptc * ts.y + pts * ts.x;
                ptc = nc; pts = ns;
            }
        }

        const size_t TOT = (size_t)SS * BB * AA * SL;
        size_t off = ((size_t)sb * AA + a) * SL + (size_t)l0;
        *(float4*)(out + off)       = outr;
        *(float4*)(out + TOT + off) = outi;
    }
}

// ---------------------------------------------------------------------------
extern "C" void kernel_launch(void* const* d_in, const int* in_sizes, int n_in,
                              void* d_out, int out_size) {
    (void)in_sizes; (void)n_in; (void)out_size;
    const float* lsr = (const float*)d_in[0];
    const float* lsi = (const float*)d_in[1];
    const int*   cs  = (const int*)d_in[2];
    float*       out = (float*)d_out;

    cudaFuncSetAttribute(k_main, cudaFuncAttributeMaxDynamicSharedMemorySize, SMEM_DYN);

    k_main<<<SS * BB, 256, SMEM_DYN>>>(lsr, lsi, cs);
    k_final<<<BB * AA * NTILE, 256>>>(lsr, lsi, out);
}

// round 16
// speedup vs baseline: 1.0843x; 1.0042x over previous
#include <cuda_runtime.h>
#include <cstdint>

#define SL   3264            // seq length L
#define KK   12
#define LPK  (SL / KK)       // 272
#define SS   8               // streams
#define BB   64              // batch
#define AA   4               // antennas
#define RR   (SL / 4)        // 816 (L / LOCC)
#define NOFF 21              // delay candidates -10..10
#define TILE 128             // l-tile for k_final
#define NTILE 26             // ceil(3264/128)
#define PDIM 816             // decimated length L/4

#define SMEM_DYN (AA * 2 * SL * 4)   // 104448 B

// ---- scratch (device-global: allocation-free contract) ----
__device__ int    g_m[SS * BB];                   // (t_off + ideal_peak) mod L
__device__ int    g_tt[SS * BB];                  // t_off mod L
__device__ float2 g_msv[SS * BB];                 // e^{i th mm} (unused by k_final; kept)
__device__ float2 g_tsv[SS * BB];                 // e^{i th tt}
__device__ float2 g_havg[SS * BB * AA * RR];      // OCC-averaged channel, 13.4 MB

// ---- packed f32x2 helpers (sm_103a dual-lane fp32) ----
#define F2MUL(o, a, b)    asm("mul.rn.f32x2 %0, %1, %2;"      : "=l"(o) : "l"(a), "l"(b))
#define F2FMA(o, a, b, c) asm("fma.rn.f32x2 %0, %1, %2, %3;"  : "=l"(o) : "l"(a), "l"(b), "l"(c))
#define F2ADD(o, a, b)    asm("add.rn.f32x2 %0, %1, %2;"      : "=l"(o) : "l"(a), "l"(b))
#define SGNMASK 0x8000000080000000ULL

static __device__ __forceinline__ uint64_t pk2(float lo, float hi) {
    uint64_t r; asm("mov.b64 %0, {%1, %2};" : "=l"(r) : "f"(lo), "f"(hi)); return r;
}
static __device__ __forceinline__ float lo2(uint64_t v) {
    float a, b; asm("mov.b64 {%0, %1}, %2;" : "=f"(a), "=f"(b) : "l"(v)); return a;
}
static __device__ __forceinline__ float hi2(uint64_t v) {
    float a, b; asm("mov.b64 {%0, %1}, %2;" : "=f"(a), "=f"(b) : "l"(v)); return b;
}
static __device__ __forceinline__ uint64_t splat(float v) { return pk2(v, v); }

// fp32 2*pi/L, matching reference fp32 angle math
#define WF ((float)(6.283185307179586476925286766559 / 3264.0))

// fast phasor: e^{i th k}; reduce to (-pi, pi] for MUFU accuracy
static __device__ __forceinline__ float2 phasor(int k) {
    if (k > SL / 2) k -= SL;
    float s, c;
    __sincosf(WF * (float)k, &s, &c);
    return make_float2(c, s);
}

static __device__ __forceinline__ int modL(int x) { x %= SL; return x < 0 ? x + SL : x; }

// packed complex in-place multiply: (ar,ai) *= (br,bi)
#define CMUL(ar, ai, br, bi) do {            \
    uint64_t _m, _nr;                        \
    F2MUL(_m, ai, bi); _m ^= SGNMASK;        \
    F2FMA(_nr, ar, br, _m);                  \
    F2MUL(_m, ai, br);                       \
    F2FMA(ai, ar, bi, _m);                   \
    ar = _nr;                                \
} while (0)

// ---- mbarrier / TMA-bulk helpers ----
static __device__ __forceinline__ uint32_t smem_u32(const void* p) {
    uint32_t r;
    asm("{ .reg .u64 t; cvta.to.shared.u64 t, %1; cvt.u32.u64 %0, t; }" : "=r"(r) : "l"(p));
    return r;
}
#define MBAR_INIT(addr, cnt) \
    asm volatile("mbarrier.init.shared.b64 [%0], %1;" :: "r"(addr), "r"(cnt) : "memory")
#define MBAR_EXPECT_TX(addr, bytes) \
    asm volatile("mbarrier.arrive.expect_tx.shared.b64 _, [%0], %1;" :: "r"(addr), "r"(bytes) : "memory")
#define TMA_BULK_G2S(dst, src, bytes, mbar) \
    asm volatile("cp.async.bulk.shared::cta.global.mbarrier::complete_tx::bytes [%0], [%1], %2, [%3];" \
        :: "r"(dst), "l"(src), "r"(bytes), "r"(mbar) : "memory")
static __device__ __forceinline__ void mbar_wait0(uint32_t addr) {
    asm volatile(
        "{\n\t"
        ".reg .pred P;\n\t"
        "WAIT_%=:\n\t"
        "mbarrier.try_wait.parity.acquire.cta.shared::cta.b64 P, [%0], 0, 0x989680;\n\t"
        "@P bra.uni DONE_%=;\n\t"
        "bra.uni WAIT_%=;\n\t"
        "DONE_%=:\n\t"
        "}" :: "r"(addr) : "memory");
}

// ---------------------------------------------------------------------------
// Chebyshev accumulation chunk for one class (proven).
// ---------------------------------------------------------------------------
template <int S>
static __device__ __forceinline__ void eval_cheb(
    uint64_t Wr, uint64_t Wi, uint64_t sr, uint64_t si,
    uint64_t phir, uint64_t phii, uint64_t tc, uint64_t ntc,
    uint64_t* accr, uint64_t* acci)
{
    uint64_t m, v0r, v0i;
    F2MUL(m, Wi, si); m ^= SGNMASK;
    F2FMA(v0r, Wr, sr, m);
    F2MUL(m, Wi, sr);
    F2FMA(v0i, Wr, si, m);
    F2ADD(accr[0], accr[0], v0r);
    F2ADD(acci[0], acci[0], v0i);

    uint64_t v1r, v1i;
    F2MUL(m, v0i, phii); m ^= SGNMASK;
    F2FMA(v1r, v0r, phir, m);
    F2MUL(m, v0i, phir);
    F2FMA(v1i, v0r, phii, m);
    F2ADD(accr[1], accr[1], v1r);
    F2ADD(acci[1], acci[1], v1i);

    uint64_t pr = v0r, pi_ = v0i, cr = v1r, ci_ = v1i;
#pragma unroll
    for (int j = 2; j < S; j++) {
        uint64_t co = (j & 1) ? tc : ntc;
        uint64_t nr, ni;
        F2FMA(nr, co, cr, pr);
        F2FMA(ni, co, ci_, pi_);
        pr = cr; pi_ = ci_; cr = nr; ci_ = ni;
        F2ADD(accr[j], accr[j], nr);
        F2ADD(acci[j], acci[j], ni);
    }
}

// warp-reduce packed complex, lane0 writes |X|^2
template <int S>
static __device__ __forceinline__ void reduce_pows(
    float* powdst /*stride-4*/, const uint64_t* accr, const uint64_t* acci, int lane)
{
#pragma unroll
    for (int j = 0; j < S; j++) {
        float rr = lo2(accr[j]) + hi2(accr[j]);
        float ii = lo2(acci[j]) + hi2(acci[j]);
#pragma unroll
        for (int o = 16; o > 0; o >>= 1) {
            rr += __shfl_xor_sync(0xFFFFFFFFu, rr, o);
            ii += __shfl_xor_sync(0xFFFFFFFFu, ii, o);
        }
        if (lane == 0) powdst[4 * j] = rr * rr + ii * ii;
    }
}

// ---------------------------------------------------------------------------
// Two residue classes per warp; 12 clean iterations + 1 predicated tail.
// ---------------------------------------------------------------------------
template <int PARITY>
static __device__ __forceinline__ void do_class2(
    const float* br, const float* bi,   // smem, 3264 floats each
    int n0, int lane, float* powrow)
{
    constexpr int SA   = 5;
    constexpr int SB   = (PARITY == 0) ? 6 : 5;
    constexpr int DMA  = (PARITY == 0) ? -8  : -7;
    constexpr int DMB  = (PARITY == 0) ? -10 : -9;
    constexpr int OFFA = DMA + 10;   // 2 or 3
    constexpr int OFFB = DMB + 10;   // 0 or 1

    const int p0 = 2 * lane;     // packed pair (p0, p0+1); stride 64/iter
    const int fA = n0 + DMA;
    const int fB = n0 + DMB;

    float2 ea = phasor(modL(fA * p0)), eb = phasor(modL(fA * (p0 + 1)));
    uint64_t sAr = pk2(ea.x, eb.x), sAi = pk2(ea.y, eb.y);
    ea = phasor(modL(fB * p0)); eb = phasor(modL(fB * (p0 + 1)));
    uint64_t sBr = pk2(ea.x, eb.x), sBi = pk2(ea.y, eb.y);

    float2 st = phasor(modL(fA * 64));
    uint64_t stAr = splat(st.x), stAi = splat(st.y);
    st = phasor(modL(fB * 64));
    uint64_t stBr = splat(st.x), stBi = splat(st.y);

    float2 pa = phasor(4 * p0), pb = phasor(4 * p0 + 4);
    uint64_t phir = pk2(pa.x, pb.x), phii = pk2(pa.y, pb.y);
    float2 psc = phasor(256);
    uint64_t pstr = splat(psc.x), psti = splat(psc.y);

    uint64_t aAr[SA], aAi[SA], aBr[SB], aBi[SB];
#pragma unroll
    for (int j = 0; j < SA; j++) { aAr[j] = aAi[j] = 0ULL; }
#pragma unroll
    for (int j = 0; j < SB; j++) { aBr[j] = aBi[j] = 0ULL; }

    int p = p0;
#pragma unroll 1
    for (int it = 0; it < 13; ++it, p += 64) {
        uint64_t xr0, xr1, xr2, xr3, xi0, xi1, xi2, xi3;
        if (it < 12) {          // p <= 62 + 11*64 = 766 < 816: always valid
            xr0 = *(const uint64_t*)(br + p);
            xr1 = *(const uint64_t*)(br + p + PDIM);
            xr2 = *(const uint64_t*)(br + p + 2 * PDIM);
            xr3 = *(const uint64_t*)(br + p + 3 * PDIM);
            xi0 = *(const uint64_t*)(bi + p);
            xi1 = *(const uint64_t*)(bi + p + PDIM);
            xi2 = *(const uint64_t*)(bi + p + 2 * PDIM);
            xi3 = *(const uint64_t*)(bi + p + 3 * PDIM);
        } else {                // tail: valid only for p < PDIM (lane < 24)
            const bool v = (p < PDIM);
            xr0 = v ? *(const uint64_t*)(br + p)            : 0ULL;
            xr1 = v ? *(const uint64_t*)(br + p + PDIM)     : 0ULL;
            xr2 = v ? *(const uint64_t*)(br + p + 2 * PDIM) : 0ULL;
            xr3 = v ? *(const uint64_t*)(br + p + 3 * PDIM) : 0ULL;
            xi0 = v ? *(const uint64_t*)(bi + p)            : 0ULL;
            xi1 = v ? *(const uint64_t*)(bi + p + PDIM)     : 0ULL;
            xi2 = v ? *(const uint64_t*)(bi + p + 2 * PDIM) : 0ULL;
            xi3 = v ? *(const uint64_t*)(bi + p + 3 * PDIM) : 0ULL;
        }

        uint64_t WAr, WAi, WBr, WBi;
        if (PARITY == 0) {
            uint64_t t0r, t0i, t2r, t2i;
            F2ADD(t0r, xr0, xr2); F2ADD(t0i, xi0, xi2);
            F2ADD(t2r, xr1, xr3); F2ADD(t2i, xi1, xi3);
            F2ADD(WAr, t0r, t2r); F2ADD(WAi, t0i, t2i);
            uint64_t n1 = t2r ^ SGNMASK, n2 = t2i ^ SGNMASK;
            F2ADD(WBr, t0r, n1);  F2ADD(WBi, t0i, n2);
        } else {
            uint64_t nr2 = xr2 ^ SGNMASK, ni2 = xi2 ^ SGNMASK;
            uint64_t nr3 = xr3 ^ SGNMASK, ni3 = xi3 ^ SGNMASK;
            uint64_t t1r, t1i, t3r, t3i;
            F2ADD(t1r, xr0, nr2); F2ADD(t1i, xi0, ni2);
            F2ADD(t3r, xr1, nr3); F2ADD(t3i, xi1, ni3);
            uint64_t nt3i = t3i ^ SGNMASK, nt3r = t3r ^ SGNMASK;
            F2ADD(WAr, t1r, nt3i); F2ADD(WAi, t1i, t3r);
            F2ADD(WBr, t1r, t3i);  F2ADD(WBi, t1i, nt3r);
        }

        uint64_t tc, ntc;
        F2ADD(tc, phir, phir);
        ntc = tc ^ SGNMASK;

        eval_cheb<SA>(WAr, WAi, sAr, sAi, phir, phii, tc, ntc, aAr, aAi);
        eval_cheb<SB>(WBr, WBi, sBr, sBi, phir, phii, tc, ntc, aBr, aBi);

        CMUL(sAr, sAi, stAr, stAi);
        CMUL(sBr, sBi, stBr, stBi);
        CMUL(phir, phii, pstr, psti);
    }

    reduce_pows<SA>(powrow + OFFA, aAr, aAi, lane);
    reduce_pows<SB>(powrow + OFFB, aBr, aBi, lane);
}

// ---------------------------------------------------------------------------
// k_main: TMA-bulk slice -> smem; phase A + argmax + phase B (R15, proven).
// ---------------------------------------------------------------------------
__global__ void __launch_bounds__(256)
k_main(const float* __restrict__ lsr, const float* __restrict__ lsi,
       const int* __restrict__ cs) {
    extern __shared__ float smbuf[];          // [(a*2+c) * SL], 104448 B
    __shared__ uint64_t mbar[AA];
    __shared__ float    spow[AA][NOFF];
    __shared__ float    shpow[NOFF];
    __shared__ int      sh_mm;

    const int sb   = blockIdx.x;
    const int s    = sb / BB;
    const int w    = threadIdx.x >> 5;
    const int lane = threadIdx.x & 31;

    const int ideal = ((KK - cs[s]) % KK) * LPK;   // in [0,SL), multiple of 4

    if (threadIdx.x == 0) {
#pragma unroll
        for (int a = 0; a < AA; a++) MBAR_INIT(smem_u32(&mbar[a]), 1);
    }
    __syncthreads();
    if (threadIdx.x == 0) {
#pragma unroll
        for (int a = 0; a < AA; a++) {
            uint32_t mb = smem_u32(&mbar[a]);
            MBAR_EXPECT_TX(mb, 2 * SL * 4);
            const float* srcr = lsr + ((size_t)sb * AA + a) * SL;
            const float* srci = lsi + ((size_t)sb * AA + a) * SL;
            TMA_BULK_G2S(smem_u32(smbuf + (a * 2) * SL),     srcr, SL * 4, mb);
            TMA_BULK_G2S(smem_u32(smbuf + (a * 2 + 1) * SL), srci, SL * 4, mb);
        }
    }

    // ---- phase A: one double-class job per warp ----
    const int a      = w >> 1;
    const int parity = w & 1;
    mbar_wait0(smem_u32(&mbar[a]));
    {
        const float* br = smbuf + (a * 2) * SL;
        const float* bi = smbuf + (a * 2 + 1) * SL;
        if (parity == 0) do_class2<0>(br, bi, ideal, lane, &spow[a][0]);
        else             do_class2<1>(br, bi, ideal, lane, &spow[a][0]);
    }
    __syncthreads();

    // ---- argmax over candidates (first-max tie rule) ----
    if (threadIdx.x < NOFF) {
        int d = threadIdx.x;
        shpow[d] = spow[0][d] + spow[1][d] + spow[2][d] + spow[3][d];
    }
    __syncthreads();
    if (threadIdx.x == 0) {
        int   best = 0;
        float bp   = shpow[0];
        for (int j = 1; j < NOFF; j++)
            if (shpow[j] > bp) { bp = shpow[j]; best = j; }
        int toff = best - 10;
        int mmv  = modL(toff + ideal);
        int ttv  = modL(toff);
        g_m[sb]   = mmv;
        g_tt[sb]  = ttv;
        g_msv[sb] = phasor(mmv);
        g_tsv[sb] = phasor(ttv);
        sh_mm     = mmv;
    }
    __syncthreads();

    // ---- phase B: OCC averaging from SMEM ----
    const int mmv = sh_mm;
    float2 msv = phasor(mmv);                        // e^{i th mm}
    float2 spv = phasor((mmv * 1024) % SL);          // r += 256 step
    float2 sd0 = phasor((mmv * 4 * (int)threadIdx.x) % SL);

#pragma unroll
    for (int aa = 0; aa < AA; aa++) {
        const float* br2 = smbuf + (aa * 2) * SL;
        const float* bi2 = smbuf + (aa * 2 + 1) * SL;
        float2* ho = g_havg + ((size_t)sb * AA + aa) * RR;
        float pc = sd0.x, ps = sd0.y;
        for (int r = threadIdx.x; r < RR; r += 256) {
            int l0 = 4 * r;
            float4 xr = *(const float4*)(br2 + l0);
            float4 xi = *(const float4*)(bi2 + l0);
            float xrv[4] = {xr.x, xr.y, xr.z, xr.w};
            float xiv[4] = {xi.x, xi.y, xi.z, xi.w};
            float qc = pc, qs = ps;
            float sr = 0.0f, si = 0.0f;
#pragma unroll
            for (int j = 0; j < 4; j++) {
                sr += xrv[j] * qc - xiv[j] * qs;
                si += xrv[j] * qs + xiv[j] * qc;
                if (j < 3) {
                    float nc = qc * msv.x - qs * msv.y;
                    float ns = qc * msv.y + qs * msv.x;
                    qc = nc; qs = ns;
                }
            }
            ho[r] = make_float2(sr * 0.25f, si * 0.25f);
            float nc = pc * spv.x - ps * spv.y;
            float ns = pc * spv.y + ps * spv.x;
            pc = nc; ps = ns;
        }
    }
}

// ---------------------------------------------------------------------------
// k_final: EXACT R11 version (32 regs, 87% occ — verified local optimum).
//   Warp-per-stream over a 128-l tile for one (b,a); 4 l's per thread.
// ---------------------------------------------------------------------------
__global__ void __launch_bounds__(256)
k_final(const float* __restrict__ lsr, const float* __restrict__ lsi,
        float* __restrict__ out) {
    const int blk  = blockIdx.x;
    const int ba   = blk / NTILE;
    const int tile = blk % NTILE;
    const int a    = ba % AA;
    const int b    = ba / AA;
    const int s    = threadIdx.x >> 5;   // warp = stream
    const int lane = threadIdx.x & 31;

    const int lbase = tile * TILE;
    const int l0    = lbase + lane * 4;
    const bool act  = (l0 < SL);

    __shared__ float shc[SS][2 * TILE];   // recon contributions
    __shared__ float shres[2 * TILE];     // residual

    const int sb = s * BB + b;
    const int mm = g_m[sb];
    const int tt = g_tt[sb];
    const float2* hv = g_havg + ((size_t)sb * AA + a) * RR;

    float hr[4], hi[4], pr[4], pi[4];

    if (act) {
        int g = l0 >> 2;
        float2 hm = hv[max(g - 1, 0)];
        float2 h0 = hv[g];
        float2 hp = hv[min(g + 1, RR - 1)];

        float f0 = (g > 0)      ? 0.625f : 0.0f;
        float f1 = (g > 0)      ? 0.875f : 0.0f;
        float f2 = (g < RR - 1) ? 0.125f : 0.0f;
        float f3 = (g < RR - 1) ? 0.375f : 0.0f;

        hr[0] = hm.x * (1.0f - f0) + h0.x * f0;  hi[0] = hm.y * (1.0f - f0) + h0.y * f0;
        hr[1] = hm.x * (1.0f - f1) + h0.x * f1;  hi[1] = hm.y * (1.0f - f1) + h0.y * f1;
        hr[2] = h0.x * (1.0f - f2) + hp.x * f2;  hi[2] = h0.y * (1.0f - f2) + hp.y * f2;
        hr[3] = h0.x * (1.0f - f3) + hp.x * f3;  hi[3] = h0.y * (1.0f - f3) + hp.y * f3;

        // mm*l0 <= 3263*3263 ~ 10.6M: int32-safe
        float2 pm = phasor((mm * l0) % SL);
        float2 ms = phasor(mm);
        float pmc = pm.x, pms = pm.y;

        float cr[4], cc[4];
#pragma unroll
        for (int j = 0; j < 4; j++) {
            pr[j] = pmc; pi[j] = pms;
            cr[j] = hr[j] * pmc + hi[j] * pms;   // h_interp * conj(ph_m)
            cc[j] = hi[j] * pmc - hr[j] * pms;
            if (j < 3) {
                float nc = pmc * ms.x - pms * ms.y;
                float ns = pmc * ms.y + pms * ms.x;
                pmc = nc; pms = ns;
            }
        }
        float4* dst = (float4*)&shc[s][lane * 8];
        dst[0] = make_float4(cr[0], cc[0], cr[1], cc[1]);
        dst[1] = make_float4(cr[2], cc[2], cr[3], cc[3]);
    }
    __syncthreads();

    // residual reduction
    {
        int ll   = threadIdx.x >> 1;
        int comp = threadIdx.x & 1;
        int lg   = lbase + ll;
        if (lg < SL) {
            float sum = 0.0f;
#pragma unroll
            for (int ss2 = 0; ss2 < SS; ss2++) sum += shc[ss2][ll * 2 + comp];
            const float* ls0 = comp ? lsi : lsr;
            shres[ll * 2 + comp] = ls0[(size_t)ba * SL + lg] - sum;
        }
    }
    __syncthreads();

    if (act) {
        float2 pt = phasor((tt * l0) % SL);
        float2 ts = phasor(tt);
        float ptc = pt.x, pts = pt.y;

        float4 r01 = *(float4*)&shres[lane * 8];
        float4 r23 = *(float4*)&shres[lane * 8 + 4];
        float rres[4] = {r01.x, r01.z, r23.x, r23.z};
        float rims[4] = {r01.y, r01.w, r23.y, r23.w};

        float4 outr, outi;
        float* orp = &outr.x;
        float* oip = &outi.x;
#pragma unroll
        for (int j = 0; j < 4; j++) {
            float wr = hr[j] + rres[j] * pr[j] - rims[j] * pi[j];
            float wi = hi[j] + rres[j] * pi[j] + rims[j] * pr[j];
            orp[j] = wr * ptc + wi * pts;
            oip[j] = wi * ptc - wr * pts;
            if (j < 3) {
                float nc = ptc * ts.x - pts * ts.y;
                float ns = ptc * ts.y + pts * ts.x;
                ptc = nc; pts = ns;
            }
        }

        const size_t TOT = (size_t)SS * BB * AA * SL;
        size_t off = ((size_t)sb * AA + a) * SL + (size_t)l0;
        *(float4*)(out + off)       = outr;
        *(float4*)(out + TOT + off) = outi;
    }
}

// ---------------------------------------------------------------------------
extern "C" void kernel_launch(void* const* d_in, const int* in_sizes, int n_in,
                              void* d_out, int out_size) {
    (void)in_sizes; (void)n_in; (void)out_size;
    const float* lsr = (const float*)d_in[0];
    const float* lsi = (const float*)d_in[1];
    const int*   cs  = (const int*)d_in[2];
    float*       out = (float*)d_out;

    cudaFuncSetAttribute(k_main, cudaFuncAttributeMaxDynamicSharedMemorySize, SMEM_DYN);

    k_main<<<SS * BB, 256, SMEM_DYN>>>(lsr, lsi, cs);
    k_final<<<BB * AA * NTILE, 256>>>(lsr, lsi, out);
}

// round 17
// speedup vs baseline: 1.1287x; 1.0410x over previous
#include <cuda_runtime.h>
#include <cstdint>

#define SL   3264            // seq length L
#define KK   12
#define LPK  (SL / KK)       // 272
#define SS   8               // streams
#define BB   64              // batch
#define AA   4               // antennas
#define RR   (SL / 4)        // 816 (L / LOCC)
#define NOFF 21              // delay candidates -10..10
#define TILE 128             // l-tile for k_final
#define NTILE 26             // ceil(3264/128)
#define PDIM 816             // decimated length L/4

#define SMEM_DYN (AA * 2 * SL * 4)   // 104448 B

// ---- scratch (device-global: allocation-free contract) ----
__device__ int    g_m[SS * BB];                   // (t_off + ideal_peak) mod L
__device__ int    g_tt[SS * BB];                  // t_off mod L
__device__ float2 g_havg[SS * BB * AA * RR];      // OCC-averaged channel, 13.4 MB

// ---- packed f32x2 helpers (sm_103a dual-lane fp32) ----
#define F2MUL(o, a, b)    asm("mul.rn.f32x2 %0, %1, %2;"      : "=l"(o) : "l"(a), "l"(b))
#define F2FMA(o, a, b, c) asm("fma.rn.f32x2 %0, %1, %2, %3;"  : "=l"(o) : "l"(a), "l"(b), "l"(c))
#define F2ADD(o, a, b)    asm("add.rn.f32x2 %0, %1, %2;"      : "=l"(o) : "l"(a), "l"(b))
#define SGNMASK 0x8000000080000000ULL

static __device__ __forceinline__ uint64_t pk2(float lo, float hi) {
    uint64_t r; asm("mov.b64 %0, {%1, %2};" : "=l"(r) : "f"(lo), "f"(hi)); return r;
}
static __device__ __forceinline__ float lo2(uint64_t v) {
    float a, b; asm("mov.b64 {%0, %1}, %2;" : "=f"(a), "=f"(b) : "l"(v)); return a;
}
static __device__ __forceinline__ float hi2(uint64_t v) {
    float a, b; asm("mov.b64 {%0, %1}, %2;" : "=f"(a), "=f"(b) : "l"(v)); return b;
}
static __device__ __forceinline__ uint64_t splat(float v) { return pk2(v, v); }

// fp32 2*pi/L, matching reference fp32 angle math
#define WF ((float)(6.283185307179586476925286766559 / 3264.0))

// fast phasor: e^{i th k}; reduce to (-pi, pi] for MUFU accuracy
static __device__ __forceinline__ float2 phasor(int k) {
    if (k > SL / 2) k -= SL;
    float s, c;
    __sincosf(WF * (float)k, &s, &c);
    return make_float2(c, s);
}

static __device__ __forceinline__ int modL(int x) { x %= SL; return x < 0 ? x + SL : x; }

// packed complex in-place multiply: (ar,ai) *= (br,bi)
#define CMUL(ar, ai, br, bi) do {            \
    uint64_t _m, _nr;                        \
    F2MUL(_m, ai, bi); _m ^= SGNMASK;        \
    F2FMA(_nr, ar, br, _m);                  \
    F2MUL(_m, ai, br);                       \
    F2FMA(ai, ar, bi, _m);                   \
    ar = _nr;                                \
} while (0)

// ---- mbarrier / TMA-bulk helpers ----
static __device__ __forceinline__ uint32_t smem_u32(const void* p) {
    uint32_t r;
    asm("{ .reg .u64 t; cvta.to.shared.u64 t, %1; cvt.u32.u64 %0, t; }" : "=r"(r) : "l"(p));
    return r;
}
#define MBAR_INIT(addr, cnt) \
    asm volatile("mbarrier.init.shared.b64 [%0], %1;" :: "r"(addr), "r"(cnt) : "memory")
#define MBAR_EXPECT_TX(addr, bytes) \
    asm volatile("mbarrier.arrive.expect_tx.shared.b64 _, [%0], %1;" :: "r"(addr), "r"(bytes) : "memory")
#define TMA_BULK_G2S(dst, src, bytes, mbar) \
    asm volatile("cp.async.bulk.shared::cta.global.mbarrier::complete_tx::bytes [%0], [%1], %2, [%3];" \
        :: "r"(dst), "l"(src), "r"(bytes), "r"(mbar) : "memory")
static __device__ __forceinline__ void mbar_wait0(uint32_t addr) {
    asm volatile(
        "{\n\t"
        ".reg .pred P;\n\t"
        "WAIT_%=:\n\t"
        "mbarrier.try_wait.parity.acquire.cta.shared::cta.b64 P, [%0], 0, 0x989680;\n\t"
        "@P bra.uni DONE_%=;\n\t"
        "bra.uni WAIT_%=;\n\t"
        "DONE_%=:\n\t"
        "}" :: "r"(addr) : "memory");
}

// ---------------------------------------------------------------------------
// Phase-A worker: ONE residue class for one antenna (R8 worker, smem-fed,
// with the proven 12-clean + 1-predicated-tail loop).
//   X(n0+d) = sum_p e^{i th (n0+dmin+4j) p} * W_p[k],  d = dmin + 4j
//   W_p[k]  = FFT4 output k of (z0..z3); Chebyshev 3-term chain over j with
//   alternating-sign substitution (only |acc|^2 consumed).
// ---------------------------------------------------------------------------
template <int S, int KIDX>
static __device__ __forceinline__ void do_class(
    const float* br, const float* bi,   // smem, 3264 floats each
    int n0, int dmin, int lane, float* powdst /* smem, stride-4 slots */)
{
    const int p0 = 2 * lane;     // packed pair (p0, p0+1); stride 64/iter
    const int fk = n0 + dmin;

    float2 ea = phasor(modL(fk * p0)), eb = phasor(modL(fk * (p0 + 1)));
    uint64_t sr = pk2(ea.x, eb.x), si = pk2(ea.y, eb.y);
    float2 st = phasor(modL(fk * 64));
    uint64_t str = splat(st.x), sti = splat(st.y);
    float2 pa = phasor(4 * p0), pb = phasor(4 * p0 + 4);
    uint64_t phir = pk2(pa.x, pb.x), phii = pk2(pa.y, pb.y);
    float2 psc = phasor(256);
    uint64_t pstr = splat(psc.x), psti = splat(psc.y);

    uint64_t accr[S], acci[S];
#pragma unroll
    for (int j = 0; j < S; j++) { accr[j] = acci[j] = 0ULL; }

    int p = p0;
#pragma unroll 1
    for (int it = 0; it < 13; ++it, p += 64) {
        uint64_t xr0, xr1, xr2, xr3, xi0, xi1, xi2, xi3;
        if (it < 12) {          // p <= 766 < 816: always valid
            xr0 = *(const uint64_t*)(br + p);
            xr1 = *(const uint64_t*)(br + p + PDIM);
            xr2 = *(const uint64_t*)(br + p + 2 * PDIM);
            xr3 = *(const uint64_t*)(br + p + 3 * PDIM);
            xi0 = *(const uint64_t*)(bi + p);
            xi1 = *(const uint64_t*)(bi + p + PDIM);
            xi2 = *(const uint64_t*)(bi + p + 2 * PDIM);
            xi3 = *(const uint64_t*)(bi + p + 3 * PDIM);
        } else {                // tail: valid only for p < PDIM (lane < 24)
            const bool v = (p < PDIM);
            xr0 = v ? *(const uint64_t*)(br + p)            : 0ULL;
            xr1 = v ? *(const uint64_t*)(br + p + PDIM)     : 0ULL;
            xr2 = v ? *(const uint64_t*)(br + p + 2 * PDIM) : 0ULL;
            xr3 = v ? *(const uint64_t*)(br + p + 3 * PDIM) : 0ULL;
            xi0 = v ? *(const uint64_t*)(bi + p)            : 0ULL;
            xi1 = v ? *(const uint64_t*)(bi + p + PDIM)     : 0ULL;
            xi2 = v ? *(const uint64_t*)(bi + p + 2 * PDIM) : 0ULL;
            xi3 = v ? *(const uint64_t*)(bi + p + 3 * PDIM) : 0ULL;
        }

        // FFT4 output KIDX
        uint64_t Wr, Wi;
        if (KIDX == 0) {
            uint64_t t0r, t0i, t2r, t2i;
            F2ADD(t0r, xr0, xr2); F2ADD(t0i, xi0, xi2);
            F2ADD(t2r, xr1, xr3); F2ADD(t2i, xi1, xi3);
            F2ADD(Wr, t0r, t2r);  F2ADD(Wi, t0i, t2i);
        } else if (KIDX == 2) {
            uint64_t t0r, t0i, t2r, t2i;
            F2ADD(t0r, xr0, xr2); F2ADD(t0i, xi0, xi2);
            F2ADD(t2r, xr1, xr3); F2ADD(t2i, xi1, xi3);
            t2r ^= SGNMASK; t2i ^= SGNMASK;
            F2ADD(Wr, t0r, t2r);  F2ADD(Wi, t0i, t2i);
        } else {
            uint64_t t1r, t1i, t3r, t3i;
            uint64_t nr2 = xr2 ^ SGNMASK, ni2 = xi2 ^ SGNMASK;
            uint64_t nr3 = xr3 ^ SGNMASK, ni3 = xi3 ^ SGNMASK;
            F2ADD(t1r, xr0, nr2); F2ADD(t1i, xi0, ni2);
            F2ADD(t3r, xr1, nr3); F2ADD(t3i, xi1, ni3);
            if (KIDX == 1) {   // W = t1 + i*t3
                uint64_t nt3i = t3i ^ SGNMASK;
                F2ADD(Wr, t1r, nt3i); F2ADD(Wi, t1i, t3r);
            } else {           // KIDX==3: W = t1 - i*t3
                uint64_t nt3r = t3r ^ SGNMASK;
                F2ADD(Wr, t1r, t3i);  F2ADD(Wi, t1i, nt3r);
            }
        }

        // v0 = W * s
        uint64_t m, v0r, v0i;
        F2MUL(m, Wi, si); m ^= SGNMASK;
        F2FMA(v0r, Wr, sr, m);
        F2MUL(m, Wi, sr);
        F2FMA(v0i, Wr, si, m);
        F2ADD(accr[0], accr[0], v0r);
        F2ADD(acci[0], acci[0], v0i);

        // v1 = v0 * phi
        uint64_t v1r, v1i;
        F2MUL(m, v0i, phii); m ^= SGNMASK;
        F2FMA(v1r, v0r, phir, m);
        F2MUL(m, v0i, phir);
        F2FMA(v1i, v0r, phii, m);
        F2ADD(accr[1], accr[1], v1r);
        F2ADD(acci[1], acci[1], v1i);

        // Chebyshev chain with alternating-sign substitution
        uint64_t tc, ntc;
        F2ADD(tc, phir, phir);
        ntc = tc ^ SGNMASK;
        uint64_t pr = v0r, pi_ = v0i, cr = v1r, ci_ = v1i;
#pragma unroll
        for (int j = 2; j < S; j++) {
            uint64_t co = (j & 1) ? tc : ntc;
            uint64_t nr, ni;
            F2FMA(nr, co, cr, pr);
            F2FMA(ni, co, ci_, pi_);
            pr = cr; pi_ = ci_; cr = nr; ci_ = ni;
            F2ADD(accr[j], accr[j], nr);
            F2ADD(acci[j], acci[j], ni);
        }

        CMUL(sr, si, str, sti);
        CMUL(phir, phii, pstr, psti);
    }

    // reduce: packed halves -> scalar, warp shfl-sum, lane0 writes |X|^2
#pragma unroll
    for (int j = 0; j < S; j++) {
        float rr = lo2(accr[j]) + hi2(accr[j]);
        float ii = lo2(acci[j]) + hi2(acci[j]);
#pragma unroll
        for (int o = 16; o > 0; o >>= 1) {
            rr += __shfl_xor_sync(0xFFFFFFFFu, rr, o);
            ii += __shfl_xor_sync(0xFFFFFFFFu, ii, o);
        }
        if (lane == 0) powdst[4 * j] = rr * rr + ii * ii;
    }
}

// ---------------------------------------------------------------------------
// k_main: TMA-bulk slice -> smem; phase A (512 threads: warp = antenna x
//   class, one class per warp) + argmax + phase B; 2 blocks/SM.
// ---------------------------------------------------------------------------
__global__ void __launch_bounds__(512, 2)
k_main(const float* __restrict__ lsr, const float* __restrict__ lsi,
       const int* __restrict__ cs) {
    extern __shared__ float smbuf[];          // [(a*2+c) * SL], 104448 B
    __shared__ uint64_t mbar[AA];
    __shared__ float    spow[AA][NOFF];
    __shared__ float    shpow[NOFF];
    __shared__ int      sh_mm;

    const int sb   = blockIdx.x;
    const int s    = sb / BB;
    const int w    = threadIdx.x >> 5;
    const int lane = threadIdx.x & 31;

    const int ideal = ((KK - cs[s]) % KK) * LPK;   // in [0,SL), multiple of 4

    if (threadIdx.x == 0) {
#pragma unroll
        for (int a = 0; a < AA; a++) MBAR_INIT(smem_u32(&mbar[a]), 1);
    }
    __syncthreads();
    if (threadIdx.x == 0) {
#pragma unroll
        for (int a = 0; a < AA; a++) {
            uint32_t mb = smem_u32(&mbar[a]);
            MBAR_EXPECT_TX(mb, 2 * SL * 4);
            const float* srcr = lsr + ((size_t)sb * AA + a) * SL;
            const float* srci = lsi + ((size_t)sb * AA + a) * SL;
            TMA_BULK_G2S(smem_u32(smbuf + (a * 2) * SL),     srcr, SL * 4, mb);
            TMA_BULK_G2S(smem_u32(smbuf + (a * 2 + 1) * SL), srci, SL * 4, mb);
        }
    }

    // ---- phase A: one class per warp; warp w -> antenna w>>2, class w&3 ----
    const int a = w >> 2;
    const int k = w & 3;
    mbar_wait0(smem_u32(&mbar[a]));
    {
        const float* br = smbuf + (a * 2) * SL;
        const float* bi = smbuf + (a * 2 + 1) * SL;
        float* powrow = &spow[a][0];
        // class k: candidates d = dmin_k + 4j; output slot = (dmin_k+10) + 4j
        if (k == 0)      do_class<5, 0>(br, bi, ideal,  -8, lane, powrow + 2);
        else if (k == 1) do_class<5, 1>(br, bi, ideal,  -7, lane, powrow + 3);
        else if (k == 2) do_class<6, 2>(br, bi, ideal, -10, lane, powrow + 0);
        else             do_class<5, 3>(br, bi, ideal,  -9, lane, powrow + 1);
    }
    __syncthreads();

    // ---- argmax over candidates (first-max tie rule) ----
    if (threadIdx.x < NOFF) {
        int d = threadIdx.x;
        shpow[d] = spow[0][d] + spow[1][d] + spow[2][d] + spow[3][d];
    }
    __syncthreads();
    if (threadIdx.x == 0) {
        int   best = 0;
        float bp   = shpow[0];
        for (int j = 1; j < NOFF; j++)
            if (shpow[j] > bp) { bp = shpow[j]; best = j; }
        int toff = best - 10;
        int mmv  = modL(toff + ideal);
        g_m[sb]  = mmv;
        g_tt[sb] = modL(toff);
        sh_mm    = mmv;
    }
    __syncthreads();

    // ---- phase B: OCC averaging from SMEM (512 threads) ----
    const int mmv = sh_mm;
    float2 msv = phasor(mmv);                        // e^{i th mm}
    float2 spv = phasor((mmv * 2048) % SL);          // r += 512 step (mm*4*512)
    float2 sd0 = phasor((int)(((long long)mmv * 4 * threadIdx.x) % SL));

#pragma unroll
    for (int aa = 0; aa < AA; aa++) {
        const float* br2 = smbuf + (aa * 2) * SL;
        const float* bi2 = smbuf + (aa * 2 + 1) * SL;
        float2* ho = g_havg + ((size_t)sb * AA + aa) * RR;
        float pc = sd0.x, ps = sd0.y;
        for (int r = threadIdx.x; r < RR; r += 512) {
            int l0 = 4 * r;
            float4 xr = *(const float4*)(br2 + l0);
            float4 xi = *(const float4*)(bi2 + l0);
            float xrv[4] = {xr.x, xr.y, xr.z, xr.w};
            float xiv[4] = {xi.x, xi.y, xi.z, xi.w};
            float qc = pc, qs = ps;
            float sr = 0.0f, si = 0.0f;
#pragma unroll
            for (int j = 0; j < 4; j++) {
                sr += xrv[j] * qc - xiv[j] * qs;
                si += xrv[j] * qs + xiv[j] * qc;
                if (j < 3) {
                    float nc = qc * msv.x - qs * msv.y;
                    float ns = qc * msv.y + qs * msv.x;
                    qc = nc; qs = ns;
                }
            }
            ho[r] = make_float2(sr * 0.25f, si * 0.25f);
            float nc = pc * spv.x - ps * spv.y;
            float ns = pc * spv.y + ps * spv.x;
            pc = nc; ps = ns;
        }
    }
}

// ---------------------------------------------------------------------------
// k_final: EXACT R11/R16 version (32 regs, 87% occ — verified local optimum).
// ---------------------------------------------------------------------------
__global__ void __launch_bounds__(256)
k_final(const float* __restrict__ lsr, const float* __restrict__ lsi,
        float* __restrict__ out) {
    const int blk  = blockIdx.x;
    const int ba   = blk / NTILE;
    const int tile = blk % NTILE;
    const int a    = ba % AA;
    const int b    = ba / AA;
    const int s    = threadIdx.x >> 5;   // warp = stream
    const int lane = threadIdx.x & 31;

    const int lbase = tile * TILE;
    const int l0    = lbase + lane * 4;
    const bool act  = (l0 < SL);

    __shared__ float shc[SS][2 * TILE];   // recon contributions
    __shared__ float shres[2 * TILE];     // residual

    const int sb = s * BB + b;
    const int mm = g_m[sb];
    const int tt = g_tt[sb];
    const float2* hv = g_havg + ((size_t)sb * AA + a) * RR;

    float hr[4], hi[4], pr[4], pi[4];

    if (act) {
        int g = l0 >> 2;
        float2 hm = hv[max(g - 1, 0)];
        float2 h0 = hv[g];
        float2 hp = hv[min(g + 1, RR - 1)];

        float f0 = (g > 0)      ? 0.625f : 0.0f;
        float f1 = (g > 0)      ? 0.875f : 0.0f;
        float f2 = (g < RR - 1) ? 0.125f : 0.0f;
        float f3 = (g < RR - 1) ? 0.375f : 0.0f;

        hr[0] = hm.x * (1.0f - f0) + h0.x * f0;  hi[0] = hm.y * (1.0f - f0) + h0.y * f0;
        hr[1] = hm.x * (1.0f - f1) + h0.x * f1;  hi[1] = hm.y * (1.0f - f1) + h0.y * f1;
        hr[2] = h0.x * (1.0f - f2) + hp.x * f2;  hi[2] = h0.y * (1.0f - f2) + hp.y * f2;
        hr[3] = h0.x * (1.0f - f3) + hp.x * f3;  hi[3] = h0.y * (1.0f - f3) + hp.y * f3;

        // mm*l0 <= 3263*3263 ~ 10.6M: int32-safe
        float2 pm = phasor((mm * l0) % SL);
        float2 ms = phasor(mm);
        float pmc = pm.x, pms = pm.y;

        float cr[4], cc[4];
#pragma unroll
        for (int j = 0; j < 4; j++) {
            pr[j] = pmc; pi[j] = pms;
            cr[j] = hr[j] * pmc + hi[j] * pms;   // h_interp * conj(ph_m)
            cc[j] = hi[j] * pmc - hr[j] * pms;
            if (j < 3) {
                float nc = pmc * ms.x - pms * ms.y;
                float ns = pmc * ms.y + pms * ms.x;
                pmc = nc; pms = ns;
            }
        }
        float4* dst = (float4*)&shc[s][lane * 8];
        dst[0] = make_float4(cr[0], cc[0], cr[1], cc[1]);
        dst[1] = make_float4(cr[2], cc[2], cr[3], cc[3]);
    }
    __syncthreads();

    // residual reduction
    {
        int ll   = threadIdx.x >> 1;
        int comp = threadIdx.x & 1;
        int lg   = lbase + ll;
        if (lg < SL) {
            float sum = 0.0f;
#pragma unroll
            for (int ss2 = 0; ss2 < SS; ss2++) sum += shc[ss2][ll * 2 + comp];
            const float* ls0 = comp ? lsi : lsr;
            shres[ll * 2 + comp] = ls0[(size_t)ba * SL + lg] - sum;
        }
    }
    __syncthreads();

    if (act) {
        float2 pt = phasor((tt * l0) % SL);
        float2 ts = phasor(tt);
        float ptc = pt.x, pts = pt.y;

        float4 r01 = *(float4*)&shres[lane * 8];
        float4 r23 = *(float4*)&shres[lane * 8 + 4];
        float rres[4] = {r01.x, r01.z, r23.x, r23.z};
        float rims[4] = {r01.y, r01.w, r23.y, r23.w};

        float4 outr, outi;
        float* orp = &outr.x;
        float* oip = &outi.x;
#pragma unroll
        for (int j = 0; j < 4; j++) {
            float wr = hr[j] + rres[j] * pr[j] - rims[j] * pi[j];
            float wi = hi[j] + rres[j] * pi[j] + rims[j] * pr[j];
            orp[j] = wr * ptc + wi * pts;
            oip[j] = wi * ptc - wr * pts;
            if (j < 3) {
                float nc = ptc * ts.x - pts * ts.y;
                float ns = ptc * ts.y + pts * ts.x;
                ptc = nc; pts = ns;
            }
        }

        const size_t TOT = (size_t)SS * BB * AA * SL;
        size_t off = ((size_t)sb * AA + a) * SL + (size_t)l0;
        *(float4*)(out + off)       = outr;
        *(float4*)(out + TOT + off) = outi;
    }
}

// ---------------------------------------------------------------------------
extern "C" void kernel_launch(void* const* d_in, const int* in_sizes, int n_in,
                              void* d_out, int out_size) {
    (void)in_sizes; (void)n_in; (void)out_size;
    const float* lsr = (const float*)d_in[0];
    const float* lsi = (const float*)d_in[1];
    const int*   cs  = (const int*)d_in[2];
    float*       out = (float*)d_out;

    cudaFuncSetAttribute(k_main, cudaFuncAttributeMaxDynamicSharedMemorySize, SMEM_DYN);

    k_main<<<SS * BB, 512, SMEM_DYN>>>(lsr, lsi, cs);
    k_final<<<BB * AA * NTILE, 256>>>(lsr, lsi, out);
}